// round 11
// baseline (speedup 1.0000x reference)
#include <cuda_runtime.h>
#include <cstdint>

#define SQRT2F     1.4142135623730951f
#define INVSQRT2F  0.7071067811865476f

using u32 = uint32_t; using u64 = uint64_t; using ull = unsigned long long;

// ======================= helpers =======================
__device__ __forceinline__ ull pack2(float lo, float hi) {
    ull r; asm("mov.b64 %0, {%1, %2};" : "=l"(r) : "f"(lo), "f"(hi)); return r;
}
__device__ __forceinline__ void unpack2(ull v, float& lo, float& hi) {
    asm("mov.b64 {%0, %1}, %2;" : "=f"(lo), "=f"(hi) : "l"(v));
}
__device__ __forceinline__ void unpack2u(ull v, u32& lo, u32& hi) {
    asm("mov.b64 {%0, %1}, %2;" : "=r"(lo), "=r"(hi) : "l"(v));
}
__device__ __forceinline__ void fma2(ull& d, ull a, ull b) {
    asm("fma.rn.f32x2 %0, %1, %2, %0;" : "+l"(d) : "l"(a), "l"(b));
}
__device__ __forceinline__ u32 f2tf32(float f) {
    u32 r; asm("cvt.rna.tf32.f32 %0, %1;" : "=r"(r) : "f"(f)); return r;
}
__device__ __forceinline__ u32 smem_u32(const void* p) {
    u32 a; asm("{ .reg .u64 t; cvta.to.shared.u64 t, %1; cvt.u32.u64 %0, t; }" : "=r"(a) : "l"(p));
    return a;
}
__device__ __forceinline__ void cp16(u32 dst, const void* src) {
    asm volatile("cp.async.ca.shared.global [%0], [%1], 16;" :: "r"(dst), "l"(src));
}
#define CP_COMMIT() asm volatile("cp.async.commit_group;" ::: "memory")
#define CP_WAIT(N)  asm volatile("cp.async.wait_group %0;" :: "n"(N) : "memory")

__device__ __forceinline__ void mma_tf32(float* c, const u32* a, const u32* b) {
    asm volatile("mma.sync.aligned.m16n8k8.row.col.f32.tf32.tf32.f32 "
                 "{%0,%1,%2,%3}, {%4,%5,%6,%7}, {%8,%9}, {%0,%1,%2,%3};"
                 : "+f"(c[0]), "+f"(c[1]), "+f"(c[2]), "+f"(c[3])
                 : "r"(a[0]), "r"(a[1]), "r"(a[2]), "r"(a[3]),
                   "r"(b[0]), "r"(b[1]));
}

// ======================= scratch =======================
__device__ __align__(16) float g_p1[8 * 256 * 66 * 66];        // padded conv1 input, tf32-rounded
__device__ __align__(16) float g_out1[8 * 256 * 64 * 64];      // conv1 output (after lrelu, fp32)
__device__ __align__(16) float g_up_pad[8 * 256 * 130 * 130];  // padded upsampled, tf32-rounded
__device__ __align__(16) float g_s64[8 * 128 * 64 * 64];       // 1x1 skip conv at 64x64 (fp32)
// weight tiles, k-pair interleaved: [chunk][pr=16][co=128][e=2], k = (pr>>2)*8 + (pr&3) + 4e
__device__ __align__(16) u32   g_wB1[2 * 72 * 4096];           // conv1: [cot][...]
__device__ __align__(16) u32   g_wB2[72 * 4096];               // conv2
__device__ __align__(16) float g_wskT[256 * 128];              // skip weights [ci][co], scaled

// ======================= weight prep =======================
__global__ void k_wt1(const float* __restrict__ w) {
    int idx = blockIdx.x * 256 + threadIdx.x;        // 2*72*4096 = 589824
    if (idx >= 589824) return;
    int e    = idx & 1;
    int co_l = (idx >> 1) & 127;
    int pr   = (idx >> 8) & 15;
    int rest = idx >> 12;                             // cot*72 + i
    int i    = rest % 72;
    int cot  = rest / 72;
    int k    = ((pr >> 2) << 3) + (pr & 3) + (e << 2);
    int koff = i >> 3, cic = i & 7;
    int ci = cic * 32 + k;
    int co = cot * 128 + co_l;
    g_wB1[idx] = f2tf32(w[(co * 256 + ci) * 9 + koff] * (1.0f / 48.0f));
}
__global__ void k_wt2(const float* __restrict__ w) {
    int idx = blockIdx.x * 256 + threadIdx.x;        // 72*4096 = 294912
    if (idx >= 294912) return;
    int e    = idx & 1;
    int co_l = (idx >> 1) & 127;
    int pr   = (idx >> 8) & 15;
    int i    = idx >> 12;                             // 0..71
    int k    = ((pr >> 2) << 3) + (pr & 3) + (e << 2);
    int koff = i >> 3, cic = i & 7;
    int ci = cic * 32 + k;
    g_wB2[idx] = f2tf32(w[(co_l * 256 + ci) * 9 + koff] * (1.0f / 48.0f));
}
__global__ void k_wts(const float* __restrict__ w) {
    int idx = blockIdx.x * 256 + threadIdx.x;
    if (idx >= 256 * 128) return;
    int co = idx & 127; int ci = idx >> 7;
    g_wskT[idx] = w[co * 256 + ci] * (1.0f / 16.0f);
}

// ======================= pad x into g_p1 (tf32-rounded) =======================
__global__ void k_pad1(const float* __restrict__ x) {
    int idx = blockIdx.x * 256 + threadIdx.x;        // 8*256*64*64
    int c = idx & 63, r = (idx >> 6) & 63, nc = idx >> 12;
    g_p1[(size_t)nc * 4356 + (r + 1) * 66 + (c + 1)] = __uint_as_float(f2tf32(x[idx]));
}

// ======================= mma.sync tf32 implicit-GEMM conv (3x3, pad 1) =================
// R9 structure (32x64 warp tiles, 2 blocks/SM) with k-pair-interleaved SMEM:
//   stage layout: 16 pair-rows x (128 cols x 2), row stride 264 u32.
//   element (k, col) at [pr(k)*264 + col*2 + e(k)], pr = (k>>3)*4 + (k&3), e = (k>>2)&1.
// => every mma fragment pair is one LDS.64; A producer stores STS.64.
// A: LDG reg-prefetch 1 iter ahead + STS, 2 stages. B: cp16, 3-stage ring, 2 ahead.
// smem = 5 * 4224 u32 = 84480 B dynamic.
// CONV=1: in=g_p1 (66x66 pad), out 64x64, M-tile = 2 rows x 64 cols, cot {0,1} -> g_out1
// CONV=2: in=g_up_pad (130x130 pad), out 128x128, M-tile = 1 row x 128 -> d_out (+ fused skip)
template <int CONV>
__global__ void __launch_bounds__(256, 2) k_conv_mma(const float* __restrict__ bias,
                                                     float* __restrict__ dout) {
    constexpr int PW  = (CONV == 1) ? 66 : 130;
    constexpr int PSZ = PW * PW;
    constexpr int OW  = (CONV == 1) ? 64 : 128;
    constexpr int ROWS = 128 / OW;
    constexpr int TILE = 16 * 264;                   // 4224 u32 per stage

    extern __shared__ __align__(16) u32 dynsmem[];
    const u32 sbase = smem_u32(dynsmem);

    const int tile = blockIdx.x;
    const int cot  = blockIdx.y;
    const int n    = blockIdx.z;
    const int tid  = threadIdx.x;
    const int lane = tid & 31;
    const int wid  = tid >> 5;
    const int warp_m = wid >> 1;       // 0..3
    const int warp_n = wid & 1;        // 0..1
    const int lg = lane >> 2;          // 0..7
    const int lt = lane & 3;           // 0..3

    const float* in = (CONV == 1) ? g_p1 : g_up_pad;
    const u32* wB = ((CONV == 1) ? g_wB1 + cot * 72 * 4096 : g_wB2);

    const int r0 = tile * ROWS;

    // A mapping: thread = one px of the 128-px M-tile, 16 ci per load (stride 2*PSZ)
    const int px = tid & 127;
    const int rl = (CONV == 1) ? (px >> 6) : 0;
    const int c  = px & (OW - 1);
    const int cihalf = tid >> 7;                 // 0..1  (k parity this thread owns)
    const float* a_base = in + ((size_t)(n * 256 + cihalf)) * PSZ
                             + (size_t)(r0 + rl) * PW + c;

    // B cp.async issue (chunk i -> stage st); gmem tile already pair-interleaved
    auto issueB = [&](int i, int st) {
        const u32* src = wB + i * 4096;
        u32 dstb = sbase + (u32)((2 + st) * TILE * 4);
#pragma unroll
        for (int p = 0; p < 4; p++) {
            int j = p * 256 + tid;                   // 16B chunk index (0..1023)
            int row = j >> 6, c4 = (j & 63) << 2;    // row = pr, c4 = u32 col offset
            cp16(dstb + (u32)((row * 264 + c4) << 2), src + (row << 8) + c4);
        }
        CP_COMMIT();
    };
    // A LDG into regs: rA[j] = A[k = cihalf + 2j]
    float rA[16];
    auto ldgA = [&](int i) {
        const int koff = i >> 3, cic = i & 7;
        const int ky = koff / 3, kx = koff - ky * 3;
        const float* src = a_base + (size_t)(cic * 32) * PSZ + ky * PW + kx;
#pragma unroll
        for (int j = 0; j < 16; j++) rA[j] = __ldg(src + (size_t)(2 * j) * PSZ);
    };
    // STS.64 of k-pairs (k, k+4): k = g*8 + cihalf + 2t -> rA[4g+t], rA[4g+t+2]
    auto stsA = [&](int st) {
        u32* sp = dynsmem + st * TILE;
#pragma unroll
        for (int g = 0; g < 4; g++)
#pragma unroll
            for (int t = 0; t < 2; t++) {
                const int pr = g * 4 + cihalf + 2 * t;
                const int j = 4 * g + t;
                *(ull*)&sp[pr * 264 + px * 2] = pack2(rA[j], rA[j + 2]);
            }
    };

    float acc[2][8][4];
#pragma unroll
    for (int mt = 0; mt < 2; mt++)
#pragma unroll
        for (int nt = 0; nt < 8; nt++)
#pragma unroll
            for (int q = 0; q < 4; q++) acc[mt][nt][q] = 0.0f;

    // ---- prologue ----
    issueB(0, 0);
    issueB(1, 1);
    ldgA(0); stsA(0);
    ldgA(1);
    CP_WAIT(1);
    __syncthreads();

    int stB = 0;                                     // B stage of current tile
    for (int i = 0; i < 72; i++) {
        const int stA = i & 1;
        int stB2 = stB + 2; if (stB2 >= 3) stB2 -= 3;
        if (i + 2 < 72) issueB(i + 2, stB2);

        const u32* sA = dynsmem + stA * TILE;
        const u32* sB = dynsmem + (2 + stB) * TILE;
#pragma unroll
        for (int ks = 0; ks < 4; ks++) {
            const u32* pA = sA + (ks * 4 + lt) * 264;
            const u32* pB = sB + (ks * 4 + lt) * 264;
            const int rb = warp_m * 32 + lg;
            u32 a[2][4];
#pragma unroll
            for (int mt = 0; mt < 2; mt++) {
                ull t0 = *(const ull*)&pA[(rb + mt * 16) * 2];
                ull t1 = *(const ull*)&pA[(rb + mt * 16 + 8) * 2];
                unpack2u(t0, a[mt][0], a[mt][2]);
                unpack2u(t1, a[mt][1], a[mt][3]);
            }
            const int nb = warp_n * 64 + lg;
            u32 b[8][2];
#pragma unroll
            for (int nt = 0; nt < 8; nt++) {
                ull t = *(const ull*)&pB[(nb + nt * 8) * 2];
                unpack2u(t, b[nt][0], b[nt][1]);
            }
#pragma unroll
            for (int mt = 0; mt < 2; mt++)
#pragma unroll
                for (int nt = 0; nt < 8; nt++)
                    mma_tf32(acc[mt][nt], a[mt], b[nt]);
        }

        if (i + 1 < 72) {
            stsA(stA ^ 1);                           // A(i+1) regs -> other stage
            if (i + 2 < 72) { ldgA(i + 2); CP_WAIT(1); }
            else            { CP_WAIT(0); }
            __syncthreads();                         // publish A(i+1) STS + B(i+1) cp.async
        }
        if (++stB == 3) stB = 0;
    }

    // ---- epilogue ----
    if (CONV == 1) {
#pragma unroll
        for (int mt = 0; mt < 2; mt++) {
            const int p0 = warp_m * 32 + mt * 16 + lg;
            const int p1 = p0 + 8;
            const int or0 = r0 + (p0 >> 6), oc0 = p0 & 63;
            const int or1 = r0 + (p1 >> 6), oc1 = p1 & 63;
#pragma unroll
            for (int nt = 0; nt < 8; nt++) {
                const int co = cot * 128 + warp_n * 64 + nt * 8 + lt * 2;
                const float bv0 = bias[co], bv1 = bias[co + 1];
                float v00 = acc[mt][nt][0] + bv0;  v00 = (v00 >= 0.0f ? v00 : 0.2f * v00) * SQRT2F;
                float v01 = acc[mt][nt][1] + bv1;  v01 = (v01 >= 0.0f ? v01 : 0.2f * v01) * SQRT2F;
                float v10 = acc[mt][nt][2] + bv0;  v10 = (v10 >= 0.0f ? v10 : 0.2f * v10) * SQRT2F;
                float v11 = acc[mt][nt][3] + bv1;  v11 = (v11 >= 0.0f ? v11 : 0.2f * v11) * SQRT2F;
                g_out1[((size_t)(n * 256 + co)     << 12) + (or0 << 6) + oc0] = v00;
                g_out1[((size_t)(n * 256 + co + 1) << 12) + (or0 << 6) + oc0] = v01;
                g_out1[((size_t)(n * 256 + co)     << 12) + (or1 << 6) + oc1] = v10;
                g_out1[((size_t)(n * 256 + co + 1) << 12) + (or1 << 6) + oc1] = v11;
            }
        }
    } else {
        // fused: out = (conv2_act + bilinear_up(g_s64)) / sqrt(2); row u = r0 fixed.
        const int u = r0;
        int rr0, rr1; float wr0, wr1;
        { int iu = u >> 1;
          if (u & 1) { rr0 = iu; rr1 = min(iu + 1, 63); wr0 = 0.75f; wr1 = 0.25f; }
          else       { rr0 = max(iu - 1, 0); rr1 = iu;  wr0 = 0.25f; wr1 = 0.75f; } }
#pragma unroll
        for (int mt = 0; mt < 2; mt++) {
#pragma unroll
            for (int half = 0; half < 2; half++) {
                const int p  = warp_m * 32 + mt * 16 + half * 8 + lg;  // output col v
                int cc0, cc1; float wc0, wc1;
                { int jv = p >> 1;
                  if (p & 1) { cc0 = jv; cc1 = min(jv + 1, 63); wc0 = 0.75f; wc1 = 0.25f; }
                  else       { cc0 = max(jv - 1, 0); cc1 = jv;  wc0 = 0.25f; wc1 = 0.75f; } }
                const int i00 = (rr0 << 6) + cc0, i01 = (rr0 << 6) + cc1;
                const int i10 = (rr1 << 6) + cc0, i11 = (rr1 << 6) + cc1;
#pragma unroll
                for (int nt = 0; nt < 8; nt++) {
                    const int co = warp_n * 64 + nt * 8 + lt * 2;
                    const float bv0 = bias[co], bv1 = bias[co + 1];
                    float va = acc[mt][nt][half * 2 + 0] + bv0;
                    va = (va >= 0.0f ? va : 0.2f * va) * SQRT2F;
                    float vb = acc[mt][nt][half * 2 + 1] + bv1;
                    vb = (vb >= 0.0f ? vb : 0.2f * vb) * SQRT2F;
                    const float* s0 = g_s64 + ((size_t)(n * 128 + co) << 12);
                    const float* s1 = s0 + 4096;
                    float sk0 = wr0 * (wc0 * s0[i00] + wc1 * s0[i01])
                              + wr1 * (wc0 * s0[i10] + wc1 * s0[i11]);
                    float sk1 = wr0 * (wc0 * s1[i00] + wc1 * s1[i01])
                              + wr1 * (wc0 * s1[i10] + wc1 * s1[i11]);
                    dout[((size_t)(n * 128 + co)     << 14) + (u << 7) + p] = (va + sk0) * INVSQRT2F;
                    dout[((size_t)(n * 128 + co + 1) << 14) + (u << 7) + p] = (vb + sk1) * INVSQRT2F;
                }
            }
        }
    }
}

// ======================= bilinear 2x upsample (half-pixel, edge clamp) =================
__global__ void k_up256() {   // g_out1[.,.,64,64] -> g_up_pad interior [130x130], tf32-rounded
    int idx = blockIdx.x * 256 + threadIdx.x;
    int v = idx & 127, u = (idx >> 7) & 127, nc = idx >> 14;
    int i = u >> 1, j = v >> 1;
    int r0, r1, c0, c1; float wr0, wr1, wc0, wc1;
    if (u & 1) { r0 = i; r1 = min(i + 1, 63); wr0 = 0.75f; wr1 = 0.25f; }
    else       { r0 = max(i - 1, 0); r1 = i;  wr0 = 0.25f; wr1 = 0.75f; }
    if (v & 1) { c0 = j; c1 = min(j + 1, 63); wc0 = 0.75f; wc1 = 0.25f; }
    else       { c0 = max(j - 1, 0); c1 = j;  wc0 = 0.25f; wc1 = 0.75f; }
    const float* b = g_out1 + ((size_t)nc << 12);
    float val = wr0 * (wc0 * b[(r0 << 6) + c0] + wc1 * b[(r0 << 6) + c1])
              + wr1 * (wc0 * b[(r1 << 6) + c0] + wc1 * b[(r1 << 6) + c1]);
    g_up_pad[(size_t)nc * 16900 + (u + 1) * 130 + (v + 1)] = __uint_as_float(f2tf32(val));
}

// ======================= skip 1x1 conv at 64x64 (256->128), fp32 f32x2 =================
__global__ void __launch_bounds__(256) k_skip(const float* __restrict__ x) {
    const int n = blockIdx.z, cot = blockIdx.y;
    const int px0 = blockIdx.x * 64;
    const int tid = threadIdx.x;
    const int co_sub = tid >> 4, pxg = tid & 15;
    const int cobase = co_sub * 4, pxb = pxg * 4;
    __shared__ __align__(16) float s_x[16][64];
    __shared__ __align__(16) float s_w[16][64];
    ull acc[2][4];
#pragma unroll
    for (int p = 0; p < 2; p++)
#pragma unroll
        for (int j = 0; j < 4; j++) acc[p][j] = 0ull;

    for (int ci0 = 0; ci0 < 256; ci0 += 16) {
        __syncthreads();
        for (int i = tid; i < 1024; i += 256) {
            int ci_l = i >> 6, p = i & 63;
            s_x[ci_l][p] = x[((n * 256 + ci0 + ci_l) << 12) + px0 + p];
            s_w[ci_l][p] = g_wskT[(ci0 + ci_l) * 128 + cot * 64 + p];
        }
        __syncthreads();
#pragma unroll 4
        for (int ci = 0; ci < 16; ci++) {
            ull w0 = *(const ull*)&s_w[ci][cobase];
            ull w1 = *(const ull*)&s_w[ci][cobase + 2];
#pragma unroll
            for (int j = 0; j < 4; j++) {
                float v = s_x[ci][pxb + j];
                ull vb = pack2(v, v);
                fma2(acc[0][j], vb, w0);
                fma2(acc[1][j], vb, w1);
            }
        }
    }
#pragma unroll
    for (int p = 0; p < 2; p++) {
        int co = cot * 64 + cobase + 2 * p;
#pragma unroll
        for (int j = 0; j < 4; j++) {
            float lo, hi; unpack2(acc[p][j], lo, hi);
            g_s64[((n * 128 + co)     << 12) + px0 + pxb + j] = lo;
            g_s64[((n * 128 + co + 1) << 12) + px0 + pxb + j] = hi;
        }
    }
}

// ======================= launch =======================
extern "C" void kernel_launch(void* const* d_in, const int* in_sizes, int n_in,
                              void* d_out, int out_size) {
    const float* x   = (const float*)d_in[0];
    const float* w1  = (const float*)d_in[1];
    const float* b1  = (const float*)d_in[2];
    const float* w2  = (const float*)d_in[3];
    const float* b2  = (const float*)d_in[4];
    const float* wsk = (const float*)d_in[5];
    float* out = (float*)d_out;

    const int SMEM_CONV = 5 * 16 * 264 * 4;   // 84480 B
    cudaFuncSetAttribute(k_conv_mma<1>, cudaFuncAttributeMaxDynamicSharedMemorySize, SMEM_CONV);
    cudaFuncSetAttribute(k_conv_mma<2>, cudaFuncAttributeMaxDynamicSharedMemorySize, SMEM_CONV);

    k_wt1<<<2304, 256>>>(w1);
    k_wt2<<<1152, 256>>>(w2);
    k_wts<<<128, 256>>>(wsk);
    k_pad1<<<32768, 256>>>(x);

    k_conv_mma<1><<<dim3(32, 2, 8), 256, SMEM_CONV>>>(b1, nullptr);
    k_up256<<<131072, 256>>>();                            // -> padded g_up_pad (tf32)
    k_skip<<<dim3(64, 2, 8), 256>>>(x);
    k_conv_mma<2><<<dim3(128, 1, 8), 256, SMEM_CONV>>>(b2, out);  // conv2 + fused skip
}

// round 13
// speedup vs baseline: 1.7876x; 1.7876x over previous
#include <cuda_runtime.h>
#include <cuda_fp16.h>
#include <cstdint>

#define SQRT2F     1.4142135623730951f
#define INVSQRT2F  0.7071067811865476f

using u32 = uint32_t; using u64 = uint64_t; using ull = unsigned long long;

// ======================= helpers =======================
__device__ __forceinline__ ull pack2(float lo, float hi) {
    ull r; asm("mov.b64 %0, {%1, %2};" : "=l"(r) : "f"(lo), "f"(hi)); return r;
}
__device__ __forceinline__ void unpack2(ull v, float& lo, float& hi) {
    asm("mov.b64 {%0, %1}, %2;" : "=f"(lo), "=f"(hi) : "l"(v));
}
__device__ __forceinline__ void fma2(ull& d, ull a, ull b) {
    asm("fma.rn.f32x2 %0, %1, %2, %0;" : "+l"(d) : "l"(a), "l"(b));
}
__device__ __forceinline__ u32 packh2(float lo, float hi) {
    __half2 h = __floats2half2_rn(lo, hi);          // x = lo (low 16), y = hi
    return *(u32*)&h;
}
__device__ __forceinline__ u32 smem_u32(const void* p) {
    u32 a; asm("{ .reg .u64 t; cvta.to.shared.u64 t, %1; cvt.u32.u64 %0, t; }" : "=r"(a) : "l"(p));
    return a;
}
__device__ __forceinline__ void cp16(u32 dst, const void* src) {
    asm volatile("cp.async.ca.shared.global [%0], [%1], 16;" :: "r"(dst), "l"(src));
}
#define CP_COMMIT() asm volatile("cp.async.commit_group;" ::: "memory")
#define CP_WAIT(N)  asm volatile("cp.async.wait_group %0;" :: "n"(N) : "memory")

// m16n8k16 fp16 mma, fp32 accum
__device__ __forceinline__ void mma_f16(float* c, const u32* a, const u32* b) {
    asm volatile("mma.sync.aligned.m16n8k16.row.col.f32.f16.f16.f32 "
                 "{%0,%1,%2,%3}, {%4,%5,%6,%7}, {%8,%9}, {%0,%1,%2,%3};"
                 : "+f"(c[0]), "+f"(c[1]), "+f"(c[2]), "+f"(c[3])
                 : "r"(a[0]), "r"(a[1]), "r"(a[2]), "r"(a[3]),
                   "r"(b[0]), "r"(b[1]));
}

// ======================= scratch =======================
// fp16 ci-pair-packed padded inputs: u32 = half2{ci=2p, ci=2p+1}
__device__ __align__(16) u32   g_p1u[8 * 128 * 66 * 66];       // padded conv1 input (border 0)
__device__ __align__(16) u32   g_up_pad_u[8 * 128 * 130 * 130];// padded upsampled conv1 out
__device__ __align__(16) float g_out1[8 * 256 * 64 * 64];      // conv1 output (after lrelu, fp32)
__device__ __align__(16) float g_s64[8 * 128 * 64 * 64];       // 1x1 skip conv at 64x64 (fp32)
// weight tiles fp16 pair-packed: [chunk i][kk=32][co=128] u32, kk = ci-pair within K=64 chunk
__device__ __align__(16) u32   g_wB1[2 * 36 * 4096];           // conv1 [cot][...]
__device__ __align__(16) u32   g_wB2[36 * 4096];               // conv2
__device__ __align__(16) float g_wskT[256 * 128];              // skip weights [ci][co], scaled

// ======================= weight prep (fp16 pairs) =======================
__global__ void k_wt1(const float* __restrict__ w) {
    int idx = blockIdx.x * 256 + threadIdx.x;        // 2*36*32*128 = 294912
    if (idx >= 294912) return;
    int co_l = idx & 127;
    int kk   = (idx >> 7) & 31;
    int rest = idx >> 12;                             // cot*36 + i
    int i    = rest % 36;
    int cot  = rest / 36;
    int koff = i >> 2, cp = i & 3;
    int ci0  = 2 * (cp * 32 + kk);
    int co   = cot * 128 + co_l;
    float v0 = w[(co * 256 + ci0)     * 9 + koff] * (1.0f / 48.0f);
    float v1 = w[(co * 256 + ci0 + 1) * 9 + koff] * (1.0f / 48.0f);
    g_wB1[idx] = packh2(v0, v1);
}
__global__ void k_wt2(const float* __restrict__ w) {
    int idx = blockIdx.x * 256 + threadIdx.x;        // 36*32*128 = 147456
    if (idx >= 147456) return;
    int co_l = idx & 127;
    int kk   = (idx >> 7) & 31;
    int i    = idx >> 12;                             // 0..35
    int koff = i >> 2, cp = i & 3;
    int ci0  = 2 * (cp * 32 + kk);
    float v0 = w[(co_l * 256 + ci0)     * 9 + koff] * (1.0f / 48.0f);
    float v1 = w[(co_l * 256 + ci0 + 1) * 9 + koff] * (1.0f / 48.0f);
    g_wB2[idx] = packh2(v0, v1);
}
__global__ void k_wts(const float* __restrict__ w) {
    int idx = blockIdx.x * 256 + threadIdx.x;
    if (idx >= 256 * 128) return;
    int co = idx & 127; int ci = idx >> 7;
    g_wskT[idx] = w[co * 256 + ci] * (1.0f / 16.0f);
}

// ======================= pad x -> g_p1u (fp16 ci-pairs) =======================
__global__ void k_pad1(const float* __restrict__ x) {
    int idx = blockIdx.x * 256 + threadIdx.x;        // 8*128*64*64 = 4194304
    int c = idx & 63, r = (idx >> 6) & 63, p = (idx >> 12) & 127, n = idx >> 19;
    const float* xb = x + ((size_t)(n * 256 + 2 * p) << 12) + (r << 6) + c;
    g_p1u[(size_t)(n * 128 + p) * 4356 + (r + 1) * 66 + (c + 1)] = packh2(xb[0], xb[4096]);
}

// ======================= mma.sync fp16 implicit-GEMM conv (3x3, pad 1) =================
// K=64 per iteration (32 ci-pairs), 36 iterations. 32x64 warp tiles, 2 blocks/SM.
// A: LDG reg-prefetch 1 iter ahead + STS, 2 stages. B: cp16, 3-stage ring, 2 ahead.
// Stage = 32 kk-rows x 136 u32; smem = 5 * 4352 u32 = 87040 B dynamic.
// CONV=1: in=g_p1u (66x66 pad), out 64x64, M-tile = 2 rows x 64, cot {0,1} -> g_out1
// CONV=2: in=g_up_pad_u (130x130 pad), out 128x128, M-tile = 1 row x 128 -> d_out (+ fused skip)
template <int CONV>
__global__ void __launch_bounds__(256, 2) k_conv_mma(const float* __restrict__ bias,
                                                     float* __restrict__ dout) {
    constexpr int PW  = (CONV == 1) ? 66 : 130;
    constexpr int PSZ = PW * PW;
    constexpr int OW  = (CONV == 1) ? 64 : 128;
    constexpr int ROWS = 128 / OW;
    constexpr int TILE = 32 * 136;                   // 4352 u32 per stage

    extern __shared__ __align__(16) u32 dynsmem[];
    const u32 sbase = smem_u32(dynsmem);

    const int tile = blockIdx.x;
    const int cot  = blockIdx.y;
    const int n    = blockIdx.z;
    const int tid  = threadIdx.x;
    const int lane = tid & 31;
    const int wid  = tid >> 5;
    const int warp_m = wid >> 1;       // 0..3
    const int warp_n = wid & 1;        // 0..1
    const int lg = lane >> 2;          // 0..7
    const int lt = lane & 3;           // 0..3

    const u32* in = (CONV == 1) ? g_p1u : g_up_pad_u;
    const u32* wB = ((CONV == 1) ? g_wB1 + cot * 36 * 4096 : g_wB2);

    const int r0 = tile * ROWS;

    // A mapping: thread = one px of the 128-px M-tile; 16 kk (pairs) per load, stride 2*PSZ
    const int px = tid & 127;
    const int rl = (CONV == 1) ? (px >> 6) : 0;
    const int c  = px & (OW - 1);
    const int half = tid >> 7;                   // kk parity this thread owns
    const u32* a_base = in + ((size_t)(n * 128 + half)) * PSZ
                           + (size_t)(r0 + rl) * PW + c;

    // B cp.async issue (chunk i -> stage st): 16KB tile [kk=32][co=128]
    auto issueB = [&](int i, int st) {
        const u32* src = wB + i * 4096;
        u32 dstb = sbase + (u32)((2 + st) * TILE * 4);
#pragma unroll
        for (int p = 0; p < 4; p++) {
            int j = p * 256 + tid;                   // 16B chunk index (0..1023)
            int row = j >> 5, c4 = (j & 31) << 2;    // row = kk, c4 = u32 col
            cp16(dstb + (u32)((row * 136 + c4) << 2), src + (row << 7) + c4);
        }
        CP_COMMIT();
    };
    // A LDG into regs: rA[j] = pair kk = half + 2j of this iteration's 32 pairs
    u32 rA[16];
    auto ldgA = [&](int i) {
        const int koff = i >> 2, cp = i & 3;
        const int ky = koff / 3, kx = koff - ky * 3;
        const u32* src = a_base + (size_t)(cp * 32) * PSZ + ky * PW + kx;
#pragma unroll
        for (int j = 0; j < 16; j++) rA[j] = __ldg(src + (size_t)(2 * j) * PSZ);
    };
    auto stsA = [&](int st) {
        u32* sp = dynsmem + st * TILE + half * 136 + px;
#pragma unroll
        for (int j = 0; j < 16; j++) sp[2 * j * 136] = rA[j];
    };

    float acc[2][8][4];
#pragma unroll
    for (int mt = 0; mt < 2; mt++)
#pragma unroll
        for (int nt = 0; nt < 8; nt++)
#pragma unroll
            for (int q = 0; q < 4; q++) acc[mt][nt][q] = 0.0f;

    // ---- prologue ----
    issueB(0, 0);
    issueB(1, 1);
    ldgA(0); stsA(0);
    ldgA(1);
    CP_WAIT(1);
    __syncthreads();

    int stB = 0;
    for (int i = 0; i < 36; i++) {
        const int stA = i & 1;
        int stB2 = stB + 2; if (stB2 >= 3) stB2 -= 3;
        if (i + 2 < 36) issueB(i + 2, stB2);

        const u32* sA = dynsmem + stA * TILE;
        const u32* sB = dynsmem + (2 + stB) * TILE;
#pragma unroll
        for (int ks = 0; ks < 4; ks++) {             // 4 k-steps of K=16 (8 pairs each)
            const int kr0 = ks * 8 + lt;             // pairs lt (k 0..7)
            const int kr1 = ks * 8 + 4 + lt;         // pairs 4+lt (k 8..15)
            const int rb = warp_m * 32 + lg;
            u32 a[2][4];
#pragma unroll
            for (int mt = 0; mt < 2; mt++) {
                a[mt][0] = sA[kr0 * 136 + rb + mt * 16];
                a[mt][1] = sA[kr0 * 136 + rb + mt * 16 + 8];
                a[mt][2] = sA[kr1 * 136 + rb + mt * 16];
                a[mt][3] = sA[kr1 * 136 + rb + mt * 16 + 8];
            }
            const int nb = warp_n * 64 + lg;
            u32 b[8][2];
#pragma unroll
            for (int nt = 0; nt < 8; nt++) {
                b[nt][0] = sB[kr0 * 136 + nb + nt * 8];
                b[nt][1] = sB[kr1 * 136 + nb + nt * 8];
            }
#pragma unroll
            for (int mt = 0; mt < 2; mt++)
#pragma unroll
                for (int nt = 0; nt < 8; nt++)
                    mma_f16(acc[mt][nt], a[mt], b[nt]);
        }

        if (i + 1 < 36) {
            stsA(stA ^ 1);
            if (i + 2 < 36) { ldgA(i + 2); CP_WAIT(1); }
            else            { CP_WAIT(0); }
            __syncthreads();
        }
        if (++stB == 3) stB = 0;
    }

    // ---- epilogue ----
    if (CONV == 1) {
#pragma unroll
        for (int mt = 0; mt < 2; mt++) {
            const int p0 = warp_m * 32 + mt * 16 + lg;
            const int p1 = p0 + 8;
            const int or0 = r0 + (p0 >> 6), oc0 = p0 & 63;
            const int or1 = r0 + (p1 >> 6), oc1 = p1 & 63;
#pragma unroll
            for (int nt = 0; nt < 8; nt++) {
                const int co = cot * 128 + warp_n * 64 + nt * 8 + lt * 2;
                const float bv0 = bias[co], bv1 = bias[co + 1];
                float v00 = acc[mt][nt][0] + bv0;  v00 = (v00 >= 0.0f ? v00 : 0.2f * v00) * SQRT2F;
                float v01 = acc[mt][nt][1] + bv1;  v01 = (v01 >= 0.0f ? v01 : 0.2f * v01) * SQRT2F;
                float v10 = acc[mt][nt][2] + bv0;  v10 = (v10 >= 0.0f ? v10 : 0.2f * v10) * SQRT2F;
                float v11 = acc[mt][nt][3] + bv1;  v11 = (v11 >= 0.0f ? v11 : 0.2f * v11) * SQRT2F;
                g_out1[((size_t)(n * 256 + co)     << 12) + (or0 << 6) + oc0] = v00;
                g_out1[((size_t)(n * 256 + co + 1) << 12) + (or0 << 6) + oc0] = v01;
                g_out1[((size_t)(n * 256 + co)     << 12) + (or1 << 6) + oc1] = v10;
                g_out1[((size_t)(n * 256 + co + 1) << 12) + (or1 << 6) + oc1] = v11;
            }
        }
    } else {
        // fused: out = (conv2_act + bilinear_up(g_s64)) / sqrt(2); row u = r0 fixed.
        const int u = r0;
        int rr0, rr1; float wr0, wr1;
        { int iu = u >> 1;
          if (u & 1) { rr0 = iu; rr1 = min(iu + 1, 63); wr0 = 0.75f; wr1 = 0.25f; }
          else       { rr0 = max(iu - 1, 0); rr1 = iu;  wr0 = 0.25f; wr1 = 0.75f; } }
#pragma unroll
        for (int mt = 0; mt < 2; mt++) {
#pragma unroll
            for (int half2_ = 0; half2_ < 2; half2_++) {
                const int p  = warp_m * 32 + mt * 16 + half2_ * 8 + lg;  // output col v
                int cc0, cc1; float wc0, wc1;
                { int jv = p >> 1;
                  if (p & 1) { cc0 = jv; cc1 = min(jv + 1, 63); wc0 = 0.75f; wc1 = 0.25f; }
                  else       { cc0 = max(jv - 1, 0); cc1 = jv;  wc0 = 0.25f; wc1 = 0.75f; } }
                const int i00 = (rr0 << 6) + cc0, i01 = (rr0 << 6) + cc1;
                const int i10 = (rr1 << 6) + cc0, i11 = (rr1 << 6) + cc1;
#pragma unroll
                for (int nt = 0; nt < 8; nt++) {
                    const int co = warp_n * 64 + nt * 8 + lt * 2;
                    const float bv0 = bias[co], bv1 = bias[co + 1];
                    float va = acc[mt][nt][half2_ * 2 + 0] + bv0;
                    va = (va >= 0.0f ? va : 0.2f * va) * SQRT2F;
                    float vb = acc[mt][nt][half2_ * 2 + 1] + bv1;
                    vb = (vb >= 0.0f ? vb : 0.2f * vb) * SQRT2F;
                    const float* s0 = g_s64 + ((size_t)(n * 128 + co) << 12);
                    const float* s1 = s0 + 4096;
                    float sk0 = wr0 * (wc0 * s0[i00] + wc1 * s0[i01])
                              + wr1 * (wc0 * s0[i10] + wc1 * s0[i11]);
                    float sk1 = wr0 * (wc0 * s1[i00] + wc1 * s1[i01])
                              + wr1 * (wc0 * s1[i10] + wc1 * s1[i11]);
                    dout[((size_t)(n * 128 + co)     << 14) + (u << 7) + p] = (va + sk0) * INVSQRT2F;
                    dout[((size_t)(n * 128 + co + 1) << 14) + (u << 7) + p] = (vb + sk1) * INVSQRT2F;
                }
            }
        }
    }
}

// ======================= bilinear 2x upsample -> fp16 pairs =======================
__global__ void k_up256() {   // g_out1[.,ci,64,64] -> g_up_pad_u interior, half2 ci-pairs
    int idx = blockIdx.x * 256 + threadIdx.x;        // 8*128*128*128 = 16777216
    int v = idx & 127, u = (idx >> 7) & 127, p = (idx >> 14) & 127, n = idx >> 21;
    int i = u >> 1, j = v >> 1;
    int r0, r1, c0, c1; float wr0, wr1, wc0, wc1;
    if (u & 1) { r0 = i; r1 = min(i + 1, 63); wr0 = 0.75f; wr1 = 0.25f; }
    else       { r0 = max(i - 1, 0); r1 = i;  wr0 = 0.25f; wr1 = 0.75f; }
    if (v & 1) { c0 = j; c1 = min(j + 1, 63); wc0 = 0.75f; wc1 = 0.25f; }
    else       { c0 = max(j - 1, 0); c1 = j;  wc0 = 0.25f; wc1 = 0.75f; }
    const float* b0 = g_out1 + ((size_t)(n * 256 + 2 * p) << 12);
    const float* b1 = b0 + 4096;
    float v0 = wr0 * (wc0 * b0[(r0 << 6) + c0] + wc1 * b0[(r0 << 6) + c1])
             + wr1 * (wc0 * b0[(r1 << 6) + c0] + wc1 * b0[(r1 << 6) + c1]);
    float v1 = wr0 * (wc0 * b1[(r0 << 6) + c0] + wc1 * b1[(r0 << 6) + c1])
             + wr1 * (wc0 * b1[(r1 << 6) + c0] + wc1 * b1[(r1 << 6) + c1]);
    g_up_pad_u[(size_t)(n * 128 + p) * 16900 + (u + 1) * 130 + (v + 1)] = packh2(v0, v1);
}

// ======================= skip 1x1 conv at 64x64 (256->128), fp32 f32x2 =================
__global__ void __launch_bounds__(256) k_skip(const float* __restrict__ x) {
    const int n = blockIdx.z, cot = blockIdx.y;
    const int px0 = blockIdx.x * 64;
    const int tid = threadIdx.x;
    const int co_sub = tid >> 4, pxg = tid & 15;
    const int cobase = co_sub * 4, pxb = pxg * 4;
    __shared__ __align__(16) float s_x[16][64];
    __shared__ __align__(16) float s_w[16][64];
    ull acc[2][4];
#pragma unroll
    for (int p = 0; p < 2; p++)
#pragma unroll
        for (int j = 0; j < 4; j++) acc[p][j] = 0ull;

    for (int ci0 = 0; ci0 < 256; ci0 += 16) {
        __syncthreads();
        for (int i = tid; i < 1024; i += 256) {
            int ci_l = i >> 6, p = i & 63;
            s_x[ci_l][p] = x[((n * 256 + ci0 + ci_l) << 12) + px0 + p];
            s_w[ci_l][p] = g_wskT[(ci0 + ci_l) * 128 + cot * 64 + p];
        }
        __syncthreads();
#pragma unroll 4
        for (int ci = 0; ci < 16; ci++) {
            ull w0 = *(const ull*)&s_w[ci][cobase];
            ull w1 = *(const ull*)&s_w[ci][cobase + 2];
#pragma unroll
            for (int j = 0; j < 4; j++) {
                float v = s_x[ci][pxb + j];
                ull vb = pack2(v, v);
                fma2(acc[0][j], vb, w0);
                fma2(acc[1][j], vb, w1);
            }
        }
    }
#pragma unroll
    for (int p = 0; p < 2; p++) {
        int co = cot * 64 + cobase + 2 * p;
#pragma unroll
        for (int j = 0; j < 4; j++) {
            float lo, hi; unpack2(acc[p][j], lo, hi);
            g_s64[((n * 128 + co)     << 12) + px0 + pxb + j] = lo;
            g_s64[((n * 128 + co + 1) << 12) + px0 + pxb + j] = hi;
        }
    }
}

// ======================= launch =======================
extern "C" void kernel_launch(void* const* d_in, const int* in_sizes, int n_in,
                              void* d_out, int out_size) {
    const float* x   = (const float*)d_in[0];
    const float* w1  = (const float*)d_in[1];
    const float* b1  = (const float*)d_in[2];
    const float* w2  = (const float*)d_in[3];
    const float* b2  = (const float*)d_in[4];
    const float* wsk = (const float*)d_in[5];
    float* out = (float*)d_out;

    const int SMEM_CONV = 5 * 32 * 136 * 4;   // 87040 B
    cudaFuncSetAttribute(k_conv_mma<1>, cudaFuncAttributeMaxDynamicSharedMemorySize, SMEM_CONV);
    cudaFuncSetAttribute(k_conv_mma<2>, cudaFuncAttributeMaxDynamicSharedMemorySize, SMEM_CONV);

    k_wt1<<<1152, 256>>>(w1);
    k_wt2<<<576, 256>>>(w2);
    k_wts<<<128, 256>>>(wsk);
    k_pad1<<<16384, 256>>>(x);

    k_conv_mma<1><<<dim3(32, 2, 8), 256, SMEM_CONV>>>(b1, nullptr);
    k_up256<<<65536, 256>>>();                             // -> g_up_pad_u (fp16 pairs)
    k_skip<<<dim3(64, 2, 8), 256>>>(x);
    k_conv_mma<2><<<dim3(128, 1, 8), 256, SMEM_CONV>>>(b2, out);  // conv2 + fused skip
}

// round 14
// speedup vs baseline: 1.8675x; 1.0447x over previous
#include <cuda_runtime.h>
#include <cuda_fp16.h>
#include <cstdint>

#define SQRT2F     1.4142135623730951f
#define INVSQRT2F  0.7071067811865476f

using u32 = uint32_t; using u64 = uint64_t; using ull = unsigned long long;

// ======================= helpers =======================
__device__ __forceinline__ ull pack2(float lo, float hi) {
    ull r; asm("mov.b64 %0, {%1, %2};" : "=l"(r) : "f"(lo), "f"(hi)); return r;
}
__device__ __forceinline__ void unpack2(ull v, float& lo, float& hi) {
    asm("mov.b64 {%0, %1}, %2;" : "=f"(lo), "=f"(hi) : "l"(v));
}
__device__ __forceinline__ void fma2(ull& d, ull a, ull b) {
    asm("fma.rn.f32x2 %0, %1, %2, %0;" : "+l"(d) : "l"(a), "l"(b));
}
__device__ __forceinline__ u32 packh2(float lo, float hi) {
    __half2 h = __floats2half2_rn(lo, hi);
    return *(u32*)&h;
}
__device__ __forceinline__ float2 uph2(u32 v) {
    __half2 h = *(__half2*)&v;
    return __half22float2(h);
}
__device__ __forceinline__ u32 smem_u32(const void* p) {
    u32 a; asm("{ .reg .u64 t; cvta.to.shared.u64 t, %1; cvt.u32.u64 %0, t; }" : "=r"(a) : "l"(p));
    return a;
}
__device__ __forceinline__ void cp16(u32 dst, const void* src) {
    asm volatile("cp.async.ca.shared.global [%0], [%1], 16;" :: "r"(dst), "l"(src));
}
#define CP_COMMIT() asm volatile("cp.async.commit_group;" ::: "memory")
#define CP_WAIT(N)  asm volatile("cp.async.wait_group %0;" :: "n"(N) : "memory")

// m16n8k16 fp16 mma, fp32 accum
__device__ __forceinline__ void mma_f16(float* c, const u32* a, const u32* b) {
    asm volatile("mma.sync.aligned.m16n8k16.row.col.f32.f16.f16.f32 "
                 "{%0,%1,%2,%3}, {%4,%5,%6,%7}, {%8,%9}, {%0,%1,%2,%3};"
                 : "+f"(c[0]), "+f"(c[1]), "+f"(c[2]), "+f"(c[3])
                 : "r"(a[0]), "r"(a[1]), "r"(a[2]), "r"(a[3]),
                   "r"(b[0]), "r"(b[1]));
}

// ======================= scratch =======================
__device__ __align__(16) u32   g_p1u[8 * 128 * 66 * 66];       // padded conv1 input, fp16 ci-pairs
__device__ __align__(16) u32   g_out1h[8 * 128 * 64 * 64];     // conv1 out (lrelu), fp16 co-pairs
__device__ __align__(16) u32   g_up_pad_u[8 * 128 * 130 * 130];// padded upsampled, fp16 pairs
__device__ __align__(16) float g_s64[8 * 128 * 64 * 64];       // 1x1 skip conv at 64x64 (fp32)
__device__ __align__(16) u32   g_wB1[2 * 36 * 4096];           // conv1 wts fp16 pairs [cot][chunk][kk][co]
__device__ __align__(16) u32   g_wB2[36 * 4096];               // conv2 wts
__device__ __align__(16) float g_wskT[256 * 128];              // skip weights [ci][co], scaled

// ======================= merged prep: pad + 3 weight transforms =======================
// grid: [0,16384) pad1 | [16384,17536) wt1 | [17536,18112) wt2 | [18112,18240) wts
__global__ void k_prep(const float* __restrict__ x,  const float* __restrict__ w1,
                       const float* __restrict__ w2, const float* __restrict__ wsk) {
    int b = blockIdx.x;
    int tid = threadIdx.x;
    if (b < 16384) {                                  // pad x -> g_p1u (fp16 ci-pairs)
        int idx = b * 256 + tid;                      // 8*128*64*64
        int c = idx & 63, r = (idx >> 6) & 63, p = (idx >> 12) & 127, n = idx >> 19;
        const float* xb = x + ((size_t)(n * 256 + 2 * p) << 12) + (r << 6) + c;
        g_p1u[(size_t)(n * 128 + p) * 4356 + (r + 1) * 66 + (c + 1)] = packh2(xb[0], xb[4096]);
    } else if (b < 17536) {                           // wt1
        int idx = (b - 16384) * 256 + tid;            // 2*36*32*128 = 294912
        int co_l = idx & 127;
        int kk   = (idx >> 7) & 31;
        int rest = idx >> 12;                          // cot*36 + i
        int i    = rest % 36;
        int cot  = rest / 36;
        int koff = i >> 2, cp = i & 3;
        int ci0  = 2 * (cp * 32 + kk);
        int co   = cot * 128 + co_l;
        float v0 = w1[(co * 256 + ci0)     * 9 + koff] * (1.0f / 48.0f);
        float v1 = w1[(co * 256 + ci0 + 1) * 9 + koff] * (1.0f / 48.0f);
        g_wB1[idx] = packh2(v0, v1);
    } else if (b < 18112) {                           // wt2
        int idx = (b - 17536) * 256 + tid;            // 36*32*128 = 147456
        int co_l = idx & 127;
        int kk   = (idx >> 7) & 31;
        int i    = idx >> 12;
        int koff = i >> 2, cp = i & 3;
        int ci0  = 2 * (cp * 32 + kk);
        float v0 = w2[(co_l * 256 + ci0)     * 9 + koff] * (1.0f / 48.0f);
        float v1 = w2[(co_l * 256 + ci0 + 1) * 9 + koff] * (1.0f / 48.0f);
        g_wB2[idx] = packh2(v0, v1);
    } else {                                          // wts
        int idx = (b - 18112) * 256 + tid;            // 32768
        int co = idx & 127; int ci = idx >> 7;
        g_wskT[idx] = wsk[co * 256 + ci] * (1.0f / 16.0f);
    }
}

// ======================= conv1 (fp16 implicit GEMM) + skip (role-split grid) ==========
// blockIdx.x < 64: conv1 tile (tile = x&31, cot = x>>5), M=128 (2 rows x 64), N=128.
// blockIdx.x >= 64: skip 1x1 conv block (s = x-64: px_tile = s&63, cot = s>>6).
__global__ void __launch_bounds__(256, 2) k_conv1s(const float* __restrict__ bias,
                                                   const float* __restrict__ x) {
    const int n   = blockIdx.z;
    const int tid = threadIdx.x;

    if (blockIdx.x >= 64) {
        // ---------------- skip: 1x1 conv at 64x64 (256->128), fp32 f32x2 ----------------
        const int s   = blockIdx.x - 64;
        const int cot = s >> 6;
        const int px0 = (s & 63) * 64;
        const int co_sub = tid >> 4, pxg = tid & 15;
        const int cobase = co_sub * 4, pxb = pxg * 4;
        __shared__ __align__(16) float s_x[16][64];
        __shared__ __align__(16) float s_w[16][64];
        ull acc[2][4];
#pragma unroll
        for (int p = 0; p < 2; p++)
#pragma unroll
            for (int j = 0; j < 4; j++) acc[p][j] = 0ull;

        for (int ci0 = 0; ci0 < 256; ci0 += 16) {
            __syncthreads();
            for (int i = tid; i < 1024; i += 256) {
                int ci_l = i >> 6, p = i & 63;
                s_x[ci_l][p] = x[((n * 256 + ci0 + ci_l) << 12) + px0 + p];
                s_w[ci_l][p] = g_wskT[(ci0 + ci_l) * 128 + cot * 64 + p];
            }
            __syncthreads();
#pragma unroll 4
            for (int ci = 0; ci < 16; ci++) {
                ull w0 = *(const ull*)&s_w[ci][cobase];
                ull w1v = *(const ull*)&s_w[ci][cobase + 2];
#pragma unroll
                for (int j = 0; j < 4; j++) {
                    float v = s_x[ci][pxb + j];
                    ull vb = pack2(v, v);
                    fma2(acc[0][j], vb, w0);
                    fma2(acc[1][j], vb, w1v);
                }
            }
        }
#pragma unroll
        for (int p = 0; p < 2; p++) {
            int co = cot * 64 + cobase + 2 * p;
#pragma unroll
            for (int j = 0; j < 4; j++) {
                float lo, hi; unpack2(acc[p][j], lo, hi);
                g_s64[((n * 128 + co)     << 12) + px0 + pxb + j] = lo;
                g_s64[((n * 128 + co + 1) << 12) + px0 + pxb + j] = hi;
            }
        }
        return;
    }

    // ---------------- conv1: K=64/iter fp16 mma pipeline ----------------
    constexpr int PW  = 66;
    constexpr int PSZ = PW * PW;
    constexpr int TILE = 32 * 136;

    extern __shared__ __align__(16) u32 dynsmem[];
    const u32 sbase = smem_u32(dynsmem);

    const int tile = blockIdx.x & 31;
    const int cot  = blockIdx.x >> 5;
    const int lane = tid & 31;
    const int wid  = tid >> 5;
    const int warp_m = wid >> 1;
    const int warp_n = wid & 1;
    const int lg = lane >> 2;
    const int lt = lane & 3;

    const u32* wB = g_wB1 + cot * 36 * 4096;
    const int r0 = tile * 2;

    const int px = tid & 127;
    const int rl = px >> 6;
    const int c  = px & 63;
    const int half = tid >> 7;
    const u32* a_base = g_p1u + ((size_t)(n * 128 + half)) * PSZ
                              + (size_t)(r0 + rl) * PW + c;

    auto issueB = [&](int i, int st) {
        const u32* src = wB + i * 4096;
        u32 dstb = sbase + (u32)((2 + st) * TILE * 4);
#pragma unroll
        for (int p = 0; p < 4; p++) {
            int j = p * 256 + tid;
            int row = j >> 5, c4 = (j & 31) << 2;
            cp16(dstb + (u32)((row * 136 + c4) << 2), src + (row << 7) + c4);
        }
        CP_COMMIT();
    };
    u32 rA[16];
    auto ldgA = [&](int i) {
        const int koff = i >> 2, cp = i & 3;
        const int ky = koff / 3, kx = koff - ky * 3;
        const u32* src = a_base + (size_t)(cp * 32) * PSZ + ky * PW + kx;
#pragma unroll
        for (int j = 0; j < 16; j++) rA[j] = __ldg(src + (size_t)(2 * j) * PSZ);
    };
    auto stsA = [&](int st) {
        u32* sp = dynsmem + st * TILE + half * 136 + px;
#pragma unroll
        for (int j = 0; j < 16; j++) sp[2 * j * 136] = rA[j];
    };

    float acc[2][8][4];
#pragma unroll
    for (int mt = 0; mt < 2; mt++)
#pragma unroll
        for (int nt = 0; nt < 8; nt++)
#pragma unroll
            for (int q = 0; q < 4; q++) acc[mt][nt][q] = 0.0f;

    issueB(0, 0);
    issueB(1, 1);
    ldgA(0); stsA(0);
    ldgA(1);
    CP_WAIT(1);
    __syncthreads();

    int stB = 0;
    for (int i = 0; i < 36; i++) {
        const int stA = i & 1;
        int stB2 = stB + 2; if (stB2 >= 3) stB2 -= 3;
        if (i + 2 < 36) issueB(i + 2, stB2);

        const u32* sA = dynsmem + stA * TILE;
        const u32* sB = dynsmem + (2 + stB) * TILE;
#pragma unroll
        for (int ks = 0; ks < 4; ks++) {
            const int kr0 = ks * 8 + lt;
            const int kr1 = ks * 8 + 4 + lt;
            const int rb = warp_m * 32 + lg;
            u32 a[2][4];
#pragma unroll
            for (int mt = 0; mt < 2; mt++) {
                a[mt][0] = sA[kr0 * 136 + rb + mt * 16];
                a[mt][1] = sA[kr0 * 136 + rb + mt * 16 + 8];
                a[mt][2] = sA[kr1 * 136 + rb + mt * 16];
                a[mt][3] = sA[kr1 * 136 + rb + mt * 16 + 8];
            }
            const int nb = warp_n * 64 + lg;
            u32 b[8][2];
#pragma unroll
            for (int nt = 0; nt < 8; nt++) {
                b[nt][0] = sB[kr0 * 136 + nb + nt * 8];
                b[nt][1] = sB[kr1 * 136 + nb + nt * 8];
            }
#pragma unroll
            for (int mt = 0; mt < 2; mt++)
#pragma unroll
                for (int nt = 0; nt < 8; nt++)
                    mma_f16(acc[mt][nt], a[mt], b[nt]);
        }

        if (i + 1 < 36) {
            stsA(stA ^ 1);
            if (i + 2 < 36) { ldgA(i + 2); CP_WAIT(1); }
            else            { CP_WAIT(0); }
            __syncthreads();
        }
        if (++stB == 3) stB = 0;
    }

    // epilogue: bias + lrelu, write fp16 co-pairs to g_out1h
#pragma unroll
    for (int mt = 0; mt < 2; mt++) {
        const int p0 = warp_m * 32 + mt * 16 + lg;
        const int p1 = p0 + 8;
        const int or0 = r0 + (p0 >> 6), oc0 = p0 & 63;
        const int or1 = r0 + (p1 >> 6), oc1 = p1 & 63;
#pragma unroll
        for (int nt = 0; nt < 8; nt++) {
            const int co = cot * 128 + warp_n * 64 + nt * 8 + lt * 2;
            const float bv0 = bias[co], bv1 = bias[co + 1];
            float v00 = acc[mt][nt][0] + bv0;  v00 = (v00 >= 0.0f ? v00 : 0.2f * v00) * SQRT2F;
            float v01 = acc[mt][nt][1] + bv1;  v01 = (v01 >= 0.0f ? v01 : 0.2f * v01) * SQRT2F;
            float v10 = acc[mt][nt][2] + bv0;  v10 = (v10 >= 0.0f ? v10 : 0.2f * v10) * SQRT2F;
            float v11 = acc[mt][nt][3] + bv1;  v11 = (v11 >= 0.0f ? v11 : 0.2f * v11) * SQRT2F;
            const size_t pl = (size_t)(n * 128 + (co >> 1)) << 12;
            g_out1h[pl + (or0 << 6) + oc0] = packh2(v00, v01);
            g_out1h[pl + (or1 << 6) + oc1] = packh2(v10, v11);
        }
    }
}

// ======================= bilinear 2x upsample (fp16 pairs in and out) =================
__global__ void k_up256() {   // g_out1h -> g_up_pad_u interior
    int idx = blockIdx.x * 256 + threadIdx.x;        // 8*128*128*128
    int v = idx & 127, u = (idx >> 7) & 127, p = (idx >> 14) & 127, n = idx >> 21;
    int i = u >> 1, j = v >> 1;
    int r0, r1, c0, c1; float wr0, wr1, wc0, wc1;
    if (u & 1) { r0 = i; r1 = min(i + 1, 63); wr0 = 0.75f; wr1 = 0.25f; }
    else       { r0 = max(i - 1, 0); r1 = i;  wr0 = 0.25f; wr1 = 0.75f; }
    if (v & 1) { c0 = j; c1 = min(j + 1, 63); wc0 = 0.75f; wc1 = 0.25f; }
    else       { c0 = max(j - 1, 0); c1 = j;  wc0 = 0.25f; wc1 = 0.75f; }
    const u32* b = g_out1h + ((size_t)(n * 128 + p) << 12);
    float2 f00 = uph2(b[(r0 << 6) + c0]), f01 = uph2(b[(r0 << 6) + c1]);
    float2 f10 = uph2(b[(r1 << 6) + c0]), f11 = uph2(b[(r1 << 6) + c1]);
    float lo = wr0 * (wc0 * f00.x + wc1 * f01.x) + wr1 * (wc0 * f10.x + wc1 * f11.x);
    float hi = wr0 * (wc0 * f00.y + wc1 * f01.y) + wr1 * (wc0 * f10.y + wc1 * f11.y);
    g_up_pad_u[(size_t)(n * 128 + p) * 16900 + (u + 1) * 130 + (v + 1)] = packh2(lo, hi);
}

// ======================= conv2 (fp16 implicit GEMM) + fused skip-upsample =============
__global__ void __launch_bounds__(256, 2) k_conv2(const float* __restrict__ bias,
                                                  float* __restrict__ dout) {
    constexpr int PW  = 130;
    constexpr int PSZ = PW * PW;
    constexpr int TILE = 32 * 136;

    extern __shared__ __align__(16) u32 dynsmem[];
    const u32 sbase = smem_u32(dynsmem);

    const int tile = blockIdx.x;
    const int n    = blockIdx.z;
    const int tid  = threadIdx.x;
    const int lane = tid & 31;
    const int wid  = tid >> 5;
    const int warp_m = wid >> 1;
    const int warp_n = wid & 1;
    const int lg = lane >> 2;
    const int lt = lane & 3;

    const int r0 = tile;                             // 1 row per tile

    const int px = tid & 127;
    const int c  = px;
    const int half = tid >> 7;
    const u32* a_base = g_up_pad_u + ((size_t)(n * 128 + half)) * PSZ
                                   + (size_t)r0 * PW + c;

    auto issueB = [&](int i, int st) {
        const u32* src = g_wB2 + i * 4096;
        u32 dstb = sbase + (u32)((2 + st) * TILE * 4);
#pragma unroll
        for (int p = 0; p < 4; p++) {
            int j = p * 256 + tid;
            int row = j >> 5, c4 = (j & 31) << 2;
            cp16(dstb + (u32)((row * 136 + c4) << 2), src + (row << 7) + c4);
        }
        CP_COMMIT();
    };
    u32 rA[16];
    auto ldgA = [&](int i) {
        const int koff = i >> 2, cp = i & 3;
        const int ky = koff / 3, kx = koff - ky * 3;
        const u32* src = a_base + (size_t)(cp * 32) * PSZ + ky * PW + kx;
#pragma unroll
        for (int j = 0; j < 16; j++) rA[j] = __ldg(src + (size_t)(2 * j) * PSZ);
    };
    auto stsA = [&](int st) {
        u32* sp = dynsmem + st * TILE + half * 136 + px;
#pragma unroll
        for (int j = 0; j < 16; j++) sp[2 * j * 136] = rA[j];
    };

    float acc[2][8][4];
#pragma unroll
    for (int mt = 0; mt < 2; mt++)
#pragma unroll
        for (int nt = 0; nt < 8; nt++)
#pragma unroll
            for (int q = 0; q < 4; q++) acc[mt][nt][q] = 0.0f;

    issueB(0, 0);
    issueB(1, 1);
    ldgA(0); stsA(0);
    ldgA(1);
    CP_WAIT(1);
    __syncthreads();

    int stB = 0;
    for (int i = 0; i < 36; i++) {
        const int stA = i & 1;
        int stB2 = stB + 2; if (stB2 >= 3) stB2 -= 3;
        if (i + 2 < 36) issueB(i + 2, stB2);

        const u32* sA = dynsmem + stA * TILE;
        const u32* sB = dynsmem + (2 + stB) * TILE;
#pragma unroll
        for (int ks = 0; ks < 4; ks++) {
            const int kr0 = ks * 8 + lt;
            const int kr1 = ks * 8 + 4 + lt;
            const int rb = warp_m * 32 + lg;
            u32 a[2][4];
#pragma unroll
            for (int mt = 0; mt < 2; mt++) {
                a[mt][0] = sA[kr0 * 136 + rb + mt * 16];
                a[mt][1] = sA[kr0 * 136 + rb + mt * 16 + 8];
                a[mt][2] = sA[kr1 * 136 + rb + mt * 16];
                a[mt][3] = sA[kr1 * 136 + rb + mt * 16 + 8];
            }
            const int nb = warp_n * 64 + lg;
            u32 b[8][2];
#pragma unroll
            for (int nt = 0; nt < 8; nt++) {
                b[nt][0] = sB[kr0 * 136 + nb + nt * 8];
                b[nt][1] = sB[kr1 * 136 + nb + nt * 8];
            }
#pragma unroll
            for (int mt = 0; mt < 2; mt++)
#pragma unroll
                for (int nt = 0; nt < 8; nt++)
                    mma_f16(acc[mt][nt], a[mt], b[nt]);
        }

        if (i + 1 < 36) {
            stsA(stA ^ 1);
            if (i + 2 < 36) { ldgA(i + 2); CP_WAIT(1); }
            else            { CP_WAIT(0); }
            __syncthreads();
        }
        if (++stB == 3) stB = 0;
    }

    // fused: out = (conv2_act + bilinear_up(g_s64)) / sqrt(2); row u = r0.
    const int u = r0;
    int rr0, rr1; float wr0, wr1;
    { int iu = u >> 1;
      if (u & 1) { rr0 = iu; rr1 = min(iu + 1, 63); wr0 = 0.75f; wr1 = 0.25f; }
      else       { rr0 = max(iu - 1, 0); rr1 = iu;  wr0 = 0.25f; wr1 = 0.75f; } }
#pragma unroll
    for (int mt = 0; mt < 2; mt++) {
#pragma unroll
        for (int hf = 0; hf < 2; hf++) {
            const int p  = warp_m * 32 + mt * 16 + hf * 8 + lg;   // output col v
            int cc0, cc1; float wc0, wc1;
            { int jv = p >> 1;
              if (p & 1) { cc0 = jv; cc1 = min(jv + 1, 63); wc0 = 0.75f; wc1 = 0.25f; }
              else       { cc0 = max(jv - 1, 0); cc1 = jv;  wc0 = 0.25f; wc1 = 0.75f; } }
            const int i00 = (rr0 << 6) + cc0, i01 = (rr0 << 6) + cc1;
            const int i10 = (rr1 << 6) + cc0, i11 = (rr1 << 6) + cc1;
#pragma unroll
            for (int nt = 0; nt < 8; nt++) {
                const int co = warp_n * 64 + nt * 8 + lt * 2;
                const float bv0 = bias[co], bv1 = bias[co + 1];
                float va = acc[mt][nt][hf * 2 + 0] + bv0;
                va = (va >= 0.0f ? va : 0.2f * va) * SQRT2F;
                float vb = acc[mt][nt][hf * 2 + 1] + bv1;
                vb = (vb >= 0.0f ? vb : 0.2f * vb) * SQRT2F;
                const float* s0 = g_s64 + ((size_t)(n * 128 + co) << 12);
                const float* s1 = s0 + 4096;
                float sk0 = wr0 * (wc0 * s0[i00] + wc1 * s0[i01])
                          + wr1 * (wc0 * s0[i10] + wc1 * s0[i11]);
                float sk1 = wr0 * (wc0 * s1[i00] + wc1 * s1[i01])
                          + wr1 * (wc0 * s1[i10] + wc1 * s1[i11]);
                dout[((size_t)(n * 128 + co)     << 14) + (u << 7) + p] = (va + sk0) * INVSQRT2F;
                dout[((size_t)(n * 128 + co + 1) << 14) + (u << 7) + p] = (vb + sk1) * INVSQRT2F;
            }
        }
    }
}

// ======================= launch =======================
extern "C" void kernel_launch(void* const* d_in, const int* in_sizes, int n_in,
                              void* d_out, int out_size) {
    const float* x   = (const float*)d_in[0];
    const float* w1  = (const float*)d_in[1];
    const float* b1  = (const float*)d_in[2];
    const float* w2  = (const float*)d_in[3];
    const float* b2  = (const float*)d_in[4];
    const float* wsk = (const float*)d_in[5];
    float* out = (float*)d_out;

    const int SMEM_CONV = 5 * 32 * 136 * 4;   // 87040 B
    cudaFuncSetAttribute(k_conv1s, cudaFuncAttributeMaxDynamicSharedMemorySize, SMEM_CONV);
    cudaFuncSetAttribute(k_conv2,  cudaFuncAttributeMaxDynamicSharedMemorySize, SMEM_CONV);

    k_prep<<<18240, 256>>>(x, w1, w2, wsk);                    // pad + all weight prep
    k_conv1s<<<dim3(192, 1, 8), 256, SMEM_CONV>>>(b1, x);      // conv1 (x<64) + skip (x>=64)
    k_up256<<<65536, 256>>>();                                 // fp16 in/out upsample
    k_conv2<<<dim3(128, 1, 8), 256, SMEM_CONV>>>(b2, out);     // conv2 + fused skip add
}

// round 15
// speedup vs baseline: 2.0699x; 1.1084x over previous
#include <cuda_runtime.h>
#include <cuda_fp16.h>
#include <cstdint>

#define SQRT2F     1.4142135623730951f
#define INVSQRT2F  0.7071067811865476f

using u32 = uint32_t; using u64 = uint64_t; using ull = unsigned long long;

// ======================= helpers =======================
__device__ __forceinline__ ull pack2(float lo, float hi) {
    ull r; asm("mov.b64 %0, {%1, %2};" : "=l"(r) : "f"(lo), "f"(hi)); return r;
}
__device__ __forceinline__ void unpack2(ull v, float& lo, float& hi) {
    asm("mov.b64 {%0, %1}, %2;" : "=f"(lo), "=f"(hi) : "l"(v));
}
__device__ __forceinline__ void fma2(ull& d, ull a, ull b) {
    asm("fma.rn.f32x2 %0, %1, %2, %0;" : "+l"(d) : "l"(a), "l"(b));
}
__device__ __forceinline__ u32 packh2(float lo, float hi) {
    __half2 h = __floats2half2_rn(lo, hi);
    return *(u32*)&h;
}
__device__ __forceinline__ float2 uph2(u32 v) {
    __half2 h = *(__half2*)&v;
    return __half22float2(h);
}
__device__ __forceinline__ u32 smem_u32(const void* p) {
    u32 a; asm("{ .reg .u64 t; cvta.to.shared.u64 t, %1; cvt.u32.u64 %0, t; }" : "=r"(a) : "l"(p));
    return a;
}
__device__ __forceinline__ void cp16(u32 dst, const void* src) {
    asm volatile("cp.async.ca.shared.global [%0], [%1], 16;" :: "r"(dst), "l"(src));
}
#define CP_COMMIT() asm volatile("cp.async.commit_group;" ::: "memory")
#define CP_WAIT(N)  asm volatile("cp.async.wait_group %0;" :: "n"(N) : "memory")

#define LDSM4(r0, r1, r2, r3, addr) \
    asm volatile("ldmatrix.sync.aligned.m8n8.x4.shared.b16 {%0,%1,%2,%3}, [%4];" \
                 : "=r"(r0), "=r"(r1), "=r"(r2), "=r"(r3) : "r"(addr))

// m16n8k16 fp16 mma, fp32 accum
__device__ __forceinline__ void mma_f16(float* c, const u32* a, const u32* b) {
    asm volatile("mma.sync.aligned.m16n8k16.row.col.f32.f16.f16.f32 "
                 "{%0,%1,%2,%3}, {%4,%5,%6,%7}, {%8,%9}, {%0,%1,%2,%3};"
                 : "+f"(c[0]), "+f"(c[1]), "+f"(c[2]), "+f"(c[3])
                 : "r"(a[0]), "r"(a[1]), "r"(a[2]), "r"(a[3]),
                   "r"(b[0]), "r"(b[1]));
}

// ======================= scratch =======================
__device__ __align__(16) u32   g_p1u[8 * 128 * 66 * 66];       // padded conv1 input, fp16 ci-pairs
__device__ __align__(16) u32   g_out1h[8 * 128 * 64 * 64];     // conv1 out (lrelu), fp16 co-pairs
__device__ __align__(16) u32   g_up_pad_u[8 * 128 * 130 * 130];// padded upsampled, fp16 pairs
__device__ __align__(16) float g_s64[8 * 128 * 64 * 64];       // 1x1 skip conv at 64x64 (fp32)
// weight tiles fp16, co-major rows of 64 halves, 16B-chunk swizzled: chunkpos = (kk>>2) ^ (co&7)
__device__ __align__(16) u32   g_wB1[2 * 36 * 4096];           // conv1 [cot][chunk i][co][swz]
__device__ __align__(16) u32   g_wB2[36 * 4096];               // conv2
__device__ __align__(16) float g_wskT[256 * 128];              // skip weights [ci][co], scaled

// ======================= merged prep: pad + 3 weight transforms =======================
// grid: [0,16384) pad1 | [16384,17536) wt1 | [17536,18112) wt2 | [18112,18240) wts
__global__ void k_prep(const float* __restrict__ x,  const float* __restrict__ w1,
                       const float* __restrict__ w2, const float* __restrict__ wsk) {
    int b = blockIdx.x;
    int tid = threadIdx.x;
    if (b < 16384) {                                  // pad x -> g_p1u (fp16 ci-pairs)
        int idx = b * 256 + tid;                      // 8*128*64*64
        int c = idx & 63, r = (idx >> 6) & 63, p = (idx >> 12) & 127, n = idx >> 19;
        const float* xb = x + ((size_t)(n * 256 + 2 * p) << 12) + (r << 6) + c;
        g_p1u[(size_t)(n * 128 + p) * 4356 + (r + 1) * 66 + (c + 1)] = packh2(xb[0], xb[4096]);
    } else if (b < 17536) {                           // wt1: swizzled co-major tiles
        int idx = (b - 16384) * 256 + tid;            // 2*36*32*128 = 294912
        int kk   = idx & 31;
        int co_l = (idx >> 5) & 127;
        int rest = idx >> 12;                          // cot*36 + i
        int i    = rest % 36;
        int cot  = rest / 36;
        int koff = i >> 2, cp = i & 3;
        int ci0  = 2 * (cp * 32 + kk);
        int co   = cot * 128 + co_l;
        float v0 = w1[(co * 256 + ci0)     * 9 + koff] * (1.0f / 48.0f);
        float v1 = w1[(co * 256 + ci0 + 1) * 9 + koff] * (1.0f / 48.0f);
        int dst = (cot * 36 + i) * 4096 + co_l * 32 + (((kk >> 2) ^ (co_l & 7)) << 2) + (kk & 3);
        g_wB1[dst] = packh2(v0, v1);
    } else if (b < 18112) {                           // wt2
        int idx = (b - 17536) * 256 + tid;            // 36*32*128 = 147456
        int kk   = idx & 31;
        int co_l = (idx >> 5) & 127;
        int i    = idx >> 12;
        int koff = i >> 2, cp = i & 3;
        int ci0  = 2 * (cp * 32 + kk);
        float v0 = w2[(co_l * 256 + ci0)     * 9 + koff] * (1.0f / 48.0f);
        float v1 = w2[(co_l * 256 + ci0 + 1) * 9 + koff] * (1.0f / 48.0f);
        int dst = i * 4096 + co_l * 32 + (((kk >> 2) ^ (co_l & 7)) << 2) + (kk & 3);
        g_wB2[dst] = packh2(v0, v1);
    } else {                                          // wts
        int idx = (b - 18112) * 256 + tid;            // 32768
        int co = idx & 127; int ci = idx >> 7;
        g_wskT[idx] = wsk[co * 256 + ci] * (1.0f / 16.0f);
    }
}

// ======================= shared conv mainloop pieces =======================
// SMEM tile (A or B): 128 rows x 32 u32 (64 halves), 16B chunk c at position c^(row&7).
// A rows = px, B rows = co. 16KB per stage; A 2 stages + B 3 stages = 80KB.
#define TILE_U32 4096
#define TILE_B   16384

// ======================= conv1 (fp16 implicit GEMM) + skip (role-split grid) ==========
// blockIdx.x < 64: conv1 tile (tile = x&31, cot = x>>5), M=128 (2 rows x 64), N=128.
// blockIdx.x >= 64: skip 1x1 conv block (s = x-64: px_tile = s&63, cot = s>>6).
__global__ void __launch_bounds__(256, 2) k_conv1s(const float* __restrict__ bias,
                                                   const float* __restrict__ x) {
    const int n   = blockIdx.z;
    const int tid = threadIdx.x;

    if (blockIdx.x >= 64) {
        // ---------------- skip: 1x1 conv at 64x64 (256->128), fp32 f32x2 ----------------
        const int s   = blockIdx.x - 64;
        const int cot = s >> 6;
        const int px0 = (s & 63) * 64;
        const int co_sub = tid >> 4, pxg = tid & 15;
        const int cobase = co_sub * 4, pxb = pxg * 4;
        __shared__ __align__(16) float s_x[16][64];
        __shared__ __align__(16) float s_w[16][64];
        ull acc[2][4];
#pragma unroll
        for (int p = 0; p < 2; p++)
#pragma unroll
            for (int j = 0; j < 4; j++) acc[p][j] = 0ull;

        for (int ci0 = 0; ci0 < 256; ci0 += 16) {
            __syncthreads();
            for (int i = tid; i < 1024; i += 256) {
                int ci_l = i >> 6, p = i & 63;
                s_x[ci_l][p] = x[((n * 256 + ci0 + ci_l) << 12) + px0 + p];
                s_w[ci_l][p] = g_wskT[(ci0 + ci_l) * 128 + cot * 64 + p];
            }
            __syncthreads();
#pragma unroll 4
            for (int ci = 0; ci < 16; ci++) {
                ull w0 = *(const ull*)&s_w[ci][cobase];
                ull w1v = *(const ull*)&s_w[ci][cobase + 2];
#pragma unroll
                for (int j = 0; j < 4; j++) {
                    float v = s_x[ci][pxb + j];
                    ull vb = pack2(v, v);
                    fma2(acc[0][j], vb, w0);
                    fma2(acc[1][j], vb, w1v);
                }
            }
        }
#pragma unroll
        for (int p = 0; p < 2; p++) {
            int co = cot * 64 + cobase + 2 * p;
#pragma unroll
            for (int j = 0; j < 4; j++) {
                float lo, hi; unpack2(acc[p][j], lo, hi);
                g_s64[((n * 128 + co)     << 12) + px0 + pxb + j] = lo;
                g_s64[((n * 128 + co + 1) << 12) + px0 + pxb + j] = hi;
            }
        }
        return;
    }

    // ---------------- conv1: K=64/iter fp16 mma pipeline, ldmatrix fragments ----------
    constexpr int PW  = 66;
    constexpr int PSZ = PW * PW;

    extern __shared__ __align__(16) u32 dynsmem[];
    const u32 sbase = smem_u32(dynsmem);

    const int tile = blockIdx.x & 31;
    const int cot  = blockIdx.x >> 5;
    const int lane = tid & 31;
    const int wid  = tid >> 5;
    const int warp_m = wid >> 1;
    const int warp_n = wid & 1;
    const int lg = lane >> 2;
    const int lt = lane & 3;

    const u32* wB = g_wB1 + cot * 36 * 4096;
    const int r0 = tile * 2;

    // A producer mapping: thread owns px row, 16-pair half-row h
    const int px = tid & 127;
    const int rl = px >> 6;
    const int c  = px & 63;
    const int h  = tid >> 7;                   // 0/1: pairs 16h..16h+15
    const u32* a_base = g_p1u + ((size_t)(n * 128 + 16 * h)) * PSZ
                              + (size_t)(r0 + rl) * PW + c;

    auto issueB = [&](int i, int st) {
        const u32* src = wB + i * 4096;
        u32 dstb = sbase + (u32)((2 + st) * TILE_B);
#pragma unroll
        for (int p = 0; p < 4; p++) {
            int j = p * 256 + tid;
            cp16(dstb + (u32)(j << 4), src + (j << 2));
        }
        CP_COMMIT();
    };
    u32 rA[16];
    auto ldgA = [&](int i) {
        const int koff = i >> 2, cp = i & 3;
        const int ky = koff / 3, kx = koff - ky * 3;
        const u32* src = a_base + (size_t)(cp * 32) * PSZ + ky * PW + kx;
#pragma unroll
        for (int j = 0; j < 16; j++) rA[j] = __ldg(src + (size_t)j * PSZ);
    };
    auto stsA = [&](int st) {
        u32* sp = dynsmem + st * TILE_U32 + px * 32;
#pragma unroll
        for (int cch = 0; cch < 4; cch++) {
            int pos = (((4 * h + cch) ^ (px & 7)) << 2);
            *(uint4*)&sp[pos] = make_uint4(rA[4*cch], rA[4*cch+1], rA[4*cch+2], rA[4*cch+3]);
        }
    };

    // ldmatrix address precompute
    const int ar  = warp_m * 32 + (lane & 7) + ((lane >> 3) & 1) * 8;  // + mt*16
    const u32 ahi = (u32)(lane >> 4);
    const u32 ar7 = (u32)(ar & 7);
    const int br  = warp_n * 64 + (lane & 7) + ((lane >> 4) & 1) * 8;  // + ntp*16
    const u32 bhi = (u32)((lane >> 3) & 1);
    const u32 br7 = (u32)(br & 7);

    float acc[2][8][4];
#pragma unroll
    for (int mt = 0; mt < 2; mt++)
#pragma unroll
        for (int nt = 0; nt < 8; nt++)
#pragma unroll
            for (int q = 0; q < 4; q++) acc[mt][nt][q] = 0.0f;

    issueB(0, 0);
    issueB(1, 1);
    ldgA(0); stsA(0);
    ldgA(1);
    CP_WAIT(1);
    __syncthreads();

    int stB = 0;
    for (int i = 0; i < 36; i++) {
        const int stA = i & 1;
        int stB2 = stB + 2; if (stB2 >= 3) stB2 -= 3;
        if (i + 2 < 36) issueB(i + 2, stB2);

        const u32 sAb = sbase + (u32)(stA * TILE_B);
        const u32 sBb = sbase + (u32)((2 + stB) * TILE_B);
#pragma unroll
        for (int ks = 0; ks < 4; ks++) {
            u32 a[2][4], bf[8][2];
            const u32 ac = ((2 * ks + ahi) ^ ar7) << 4;
            LDSM4(a[0][0], a[0][1], a[0][2], a[0][3], sAb + (u32)(ar << 7) + ac);
            LDSM4(a[1][0], a[1][1], a[1][2], a[1][3], sAb + (u32)((ar + 16) << 7) + ac);
            const u32 bc = ((2 * ks + bhi) ^ br7) << 4;
#pragma unroll
            for (int ntp = 0; ntp < 4; ntp++) {
                LDSM4(bf[2*ntp][0], bf[2*ntp][1], bf[2*ntp+1][0], bf[2*ntp+1][1],
                      sBb + (u32)((br + ntp * 16) << 7) + bc);
            }
#pragma unroll
            for (int mt = 0; mt < 2; mt++)
#pragma unroll
                for (int nt = 0; nt < 8; nt++)
                    mma_f16(acc[mt][nt], a[mt], bf[nt]);
        }

        if (i + 1 < 36) {
            stsA(stA ^ 1);
            if (i + 2 < 36) { ldgA(i + 2); CP_WAIT(1); }
            else            { CP_WAIT(0); }
            __syncthreads();
        }
        if (++stB == 3) stB = 0;
    }

    // epilogue: bias + lrelu, write fp16 co-pairs to g_out1h
#pragma unroll
    for (int mt = 0; mt < 2; mt++) {
        const int p0 = warp_m * 32 + mt * 16 + lg;
        const int p1 = p0 + 8;
        const int or0 = r0 + (p0 >> 6), oc0 = p0 & 63;
        const int or1 = r0 + (p1 >> 6), oc1 = p1 & 63;
#pragma unroll
        for (int nt = 0; nt < 8; nt++) {
            const int co = cot * 128 + warp_n * 64 + nt * 8 + lt * 2;
            const float bv0 = bias[co], bv1 = bias[co + 1];
            float v00 = acc[mt][nt][0] + bv0;  v00 = (v00 >= 0.0f ? v00 : 0.2f * v00) * SQRT2F;
            float v01 = acc[mt][nt][1] + bv1;  v01 = (v01 >= 0.0f ? v01 : 0.2f * v01) * SQRT2F;
            float v10 = acc[mt][nt][2] + bv0;  v10 = (v10 >= 0.0f ? v10 : 0.2f * v10) * SQRT2F;
            float v11 = acc[mt][nt][3] + bv1;  v11 = (v11 >= 0.0f ? v11 : 0.2f * v11) * SQRT2F;
            const size_t pl = (size_t)(n * 128 + (co >> 1)) << 12;
            g_out1h[pl + (or0 << 6) + oc0] = packh2(v00, v01);
            g_out1h[pl + (or1 << 6) + oc1] = packh2(v10, v11);
        }
    }
}

// ======================= bilinear 2x upsample (fp16 pairs in and out) =================
__global__ void k_up256() {   // g_out1h -> g_up_pad_u interior
    int idx = blockIdx.x * 256 + threadIdx.x;        // 8*128*128*128
    int v = idx & 127, u = (idx >> 7) & 127, p = (idx >> 14) & 127, n = idx >> 21;
    int i = u >> 1, j = v >> 1;
    int r0, r1, c0, c1; float wr0, wr1, wc0, wc1;
    if (u & 1) { r0 = i; r1 = min(i + 1, 63); wr0 = 0.75f; wr1 = 0.25f; }
    else       { r0 = max(i - 1, 0); r1 = i;  wr0 = 0.25f; wr1 = 0.75f; }
    if (v & 1) { c0 = j; c1 = min(j + 1, 63); wc0 = 0.75f; wc1 = 0.25f; }
    else       { c0 = max(j - 1, 0); c1 = j;  wc0 = 0.25f; wc1 = 0.75f; }
    const u32* b = g_out1h + ((size_t)(n * 128 + p) << 12);
    float2 f00 = uph2(b[(r0 << 6) + c0]), f01 = uph2(b[(r0 << 6) + c1]);
    float2 f10 = uph2(b[(r1 << 6) + c0]), f11 = uph2(b[(r1 << 6) + c1]);
    float lo = wr0 * (wc0 * f00.x + wc1 * f01.x) + wr1 * (wc0 * f10.x + wc1 * f11.x);
    float hi = wr0 * (wc0 * f00.y + wc1 * f01.y) + wr1 * (wc0 * f10.y + wc1 * f11.y);
    g_up_pad_u[(size_t)(n * 128 + p) * 16900 + (u + 1) * 130 + (v + 1)] = packh2(lo, hi);
}

// ======================= conv2 (fp16 implicit GEMM) + fused skip-upsample =============
__global__ void __launch_bounds__(256, 2) k_conv2(const float* __restrict__ bias,
                                                  float* __restrict__ dout) {
    constexpr int PW  = 130;
    constexpr int PSZ = PW * PW;

    extern __shared__ __align__(16) u32 dynsmem[];
    const u32 sbase = smem_u32(dynsmem);

    const int tile = blockIdx.x;
    const int n    = blockIdx.z;
    const int tid  = threadIdx.x;
    const int lane = tid & 31;
    const int wid  = tid >> 5;
    const int warp_m = wid >> 1;
    const int warp_n = wid & 1;
    const int lg = lane >> 2;
    const int lt = lane & 3;

    const int r0 = tile;                             // 1 row per tile

    const int px = tid & 127;
    const int h  = tid >> 7;
    const u32* a_base = g_up_pad_u + ((size_t)(n * 128 + 16 * h)) * PSZ
                                   + (size_t)r0 * PW + px;

    auto issueB = [&](int i, int st) {
        const u32* src = g_wB2 + i * 4096;
        u32 dstb = sbase + (u32)((2 + st) * TILE_B);
#pragma unroll
        for (int p = 0; p < 4; p++) {
            int j = p * 256 + tid;
            cp16(dstb + (u32)(j << 4), src + (j << 2));
        }
        CP_COMMIT();
    };
    u32 rA[16];
    auto ldgA = [&](int i) {
        const int koff = i >> 2, cp = i & 3;
        const int ky = koff / 3, kx = koff - ky * 3;
        const u32* src = a_base + (size_t)(cp * 32) * PSZ + ky * PW + kx;
#pragma unroll
        for (int j = 0; j < 16; j++) rA[j] = __ldg(src + (size_t)j * PSZ);
    };
    auto stsA = [&](int st) {
        u32* sp = dynsmem + st * TILE_U32 + px * 32;
#pragma unroll
        for (int cch = 0; cch < 4; cch++) {
            int pos = (((4 * h + cch) ^ (px & 7)) << 2);
            *(uint4*)&sp[pos] = make_uint4(rA[4*cch], rA[4*cch+1], rA[4*cch+2], rA[4*cch+3]);
        }
    };

    const int ar  = warp_m * 32 + (lane & 7) + ((lane >> 3) & 1) * 8;
    const u32 ahi = (u32)(lane >> 4);
    const u32 ar7 = (u32)(ar & 7);
    const int br  = warp_n * 64 + (lane & 7) + ((lane >> 4) & 1) * 8;
    const u32 bhi = (u32)((lane >> 3) & 1);
    const u32 br7 = (u32)(br & 7);

    float acc[2][8][4];
#pragma unroll
    for (int mt = 0; mt < 2; mt++)
#pragma unroll
        for (int nt = 0; nt < 8; nt++)
#pragma unroll
            for (int q = 0; q < 4; q++) acc[mt][nt][q] = 0.0f;

    issueB(0, 0);
    issueB(1, 1);
    ldgA(0); stsA(0);
    ldgA(1);
    CP_WAIT(1);
    __syncthreads();

    int stB = 0;
    for (int i = 0; i < 36; i++) {
        const int stA = i & 1;
        int stB2 = stB + 2; if (stB2 >= 3) stB2 -= 3;
        if (i + 2 < 36) issueB(i + 2, stB2);

        const u32 sAb = sbase + (u32)(stA * TILE_B);
        const u32 sBb = sbase + (u32)((2 + stB) * TILE_B);
#pragma unroll
        for (int ks = 0; ks < 4; ks++) {
            u32 a[2][4], bf[8][2];
            const u32 ac = ((2 * ks + ahi) ^ ar7) << 4;
            LDSM4(a[0][0], a[0][1], a[0][2], a[0][3], sAb + (u32)(ar << 7) + ac);
            LDSM4(a[1][0], a[1][1], a[1][2], a[1][3], sAb + (u32)((ar + 16) << 7) + ac);
            const u32 bc = ((2 * ks + bhi) ^ br7) << 4;
#pragma unroll
            for (int ntp = 0; ntp < 4; ntp++) {
                LDSM4(bf[2*ntp][0], bf[2*ntp][1], bf[2*ntp+1][0], bf[2*ntp+1][1],
                      sBb + (u32)((br + ntp * 16) << 7) + bc);
            }
#pragma unroll
            for (int mt = 0; mt < 2; mt++)
#pragma unroll
                for (int nt = 0; nt < 8; nt++)
                    mma_f16(acc[mt][nt], a[mt], bf[nt]);
        }

        if (i + 1 < 36) {
            stsA(stA ^ 1);
            if (i + 2 < 36) { ldgA(i + 2); CP_WAIT(1); }
            else            { CP_WAIT(0); }
            __syncthreads();
        }
        if (++stB == 3) stB = 0;
    }

    // fused: out = (conv2_act + bilinear_up(g_s64)) / sqrt(2); row u = r0.
    const int u = r0;
    int rr0, rr1; float wr0, wr1;
    { int iu = u >> 1;
      if (u & 1) { rr0 = iu; rr1 = min(iu + 1, 63); wr0 = 0.75f; wr1 = 0.25f; }
      else       { rr0 = max(iu - 1, 0); rr1 = iu;  wr0 = 0.25f; wr1 = 0.75f; } }
#pragma unroll
    for (int mt = 0; mt < 2; mt++) {
#pragma unroll
        for (int hf = 0; hf < 2; hf++) {
            const int p  = warp_m * 32 + mt * 16 + hf * 8 + lg;   // output col v
            int cc0, cc1; float wc0, wc1;
            { int jv = p >> 1;
              if (p & 1) { cc0 = jv; cc1 = min(jv + 1, 63); wc0 = 0.75f; wc1 = 0.25f; }
              else       { cc0 = max(jv - 1, 0); cc1 = jv;  wc0 = 0.25f; wc1 = 0.75f; } }
            const int i00 = (rr0 << 6) + cc0, i01 = (rr0 << 6) + cc1;
            const int i10 = (rr1 << 6) + cc0, i11 = (rr1 << 6) + cc1;
#pragma unroll
            for (int nt = 0; nt < 8; nt++) {
                const int co = warp_n * 64 + nt * 8 + lt * 2;
                const float bv0 = bias[co], bv1 = bias[co + 1];
                float va = acc[mt][nt][hf * 2 + 0] + bv0;
                va = (va >= 0.0f ? va : 0.2f * va) * SQRT2F;
                float vb = acc[mt][nt][hf * 2 + 1] + bv1;
                vb = (vb >= 0.0f ? vb : 0.2f * vb) * SQRT2F;
                const float* s0 = g_s64 + ((size_t)(n * 128 + co) << 12);
                const float* s1 = s0 + 4096;
                float sk0 = wr0 * (wc0 * s0[i00] + wc1 * s0[i01])
                          + wr1 * (wc0 * s0[i10] + wc1 * s0[i11]);
                float sk1 = wr0 * (wc0 * s1[i00] + wc1 * s1[i01])
                          + wr1 * (wc0 * s1[i10] + wc1 * s1[i11]);
                dout[((size_t)(n * 128 + co)     << 14) + (u << 7) + p] = (va + sk0) * INVSQRT2F;
                dout[((size_t)(n * 128 + co + 1) << 14) + (u << 7) + p] = (vb + sk1) * INVSQRT2F;
            }
        }
    }
}

// ======================= launch =======================
extern "C" void kernel_launch(void* const* d_in, const int* in_sizes, int n_in,
                              void* d_out, int out_size) {
    const float* x   = (const float*)d_in[0];
    const float* w1  = (const float*)d_in[1];
    const float* b1  = (const float*)d_in[2];
    const float* w2  = (const float*)d_in[3];
    const float* b2  = (const float*)d_in[4];
    const float* wsk = (const float*)d_in[5];
    float* out = (float*)d_out;

    const int SMEM_CONV = 5 * TILE_B;   // 81920 B
    cudaFuncSetAttribute(k_conv1s, cudaFuncAttributeMaxDynamicSharedMemorySize, SMEM_CONV);
    cudaFuncSetAttribute(k_conv2,  cudaFuncAttributeMaxDynamicSharedMemorySize, SMEM_CONV);

    k_prep<<<18240, 256>>>(x, w1, w2, wsk);                    // pad + all weight prep
    k_conv1s<<<dim3(192, 1, 8), 256, SMEM_CONV>>>(b1, x);      // conv1 (x<64) + skip (x>=64)
    k_up256<<<65536, 256>>>();                                 // fp16 in/out upsample
    k_conv2<<<dim3(128, 1, 8), 256, SMEM_CONV>>>(b2, out);     // conv2 + fused skip add
}